// round 7
// baseline (speedup 1.0000x reference)
#include <cuda_runtime.h>
#include <math.h>

#define B_    16
#define N_    785
#define C_    768
#define H_    12
#define HD_   64
#define M_    (B_*N_)        // 12560
#define QKVC  (3*C_)         // 2304
#define LEFT  549
#define NM1   784
#define SCALE_ 0.125f

// output segment offsets (floats): [out | idx | index | cls_attn]
#define OFF_OUT   0
#define OFF_IDX   9646080
#define OFF_INDEX 9654864
#define OFF_CLS   16400976

// scratch (static device allocations; no runtime malloc)
__device__ float g_qkv[M_ * QKVC];                  // [B*N, 3C]
__device__ float g_attn[(size_t)B_ * H_ * N_ * N_]; // [B*H, N, N]
__device__ float g_attnout[M_ * C_];                // [B*N, C] head-interleaved
__device__ float g_ph[B_ * H_ * N_];                // cls-row softmax per head
__device__ float g_cls[B_ * NM1];
__device__ int   g_idx[B_ * LEFT];

// ---------------------------------------------------------------------------
// Cephes-style expf: bit-matches Eigen pexp / XLA-CPU vectorized exp.
// All steps fp32 FMA, fixed order.
// ---------------------------------------------------------------------------
__device__ __forceinline__ float cephes_expf(float x)
{
    x = fminf(x, 88.723164f);
    x = fmaxf(x, -87.33654f);
    float m = floorf(fmaf(x, 1.44269504088896341f, 0.5f));
    float r = fmaf(m, -0.693359375f, x);
    r = fmaf(m, 2.12194440e-4f, r);
    float r2 = r * r;
    float y = 1.9875691500E-4f;
    y = fmaf(y, r, 1.3981999507E-3f);
    y = fmaf(y, r, 8.3334519073E-3f);
    y = fmaf(y, r, 4.1665795894E-2f);
    y = fmaf(y, r, 1.6666665459E-1f);
    y = fmaf(y, r, 5.0000001201E-1f);
    y = fmaf(y, r2, r);
    y = y + 1.0f;
    int mi = (int)m;                       // m in [-126, 127] after clamp
    float s = __int_as_float((mi + 127) << 23);
    return y * s;
}

// ---------------------------------------------------------------------------
// SGEMM NT: C[m,n] = sum_k A[m,k]*Bw[n,k] (+bias[n]); 128x128x8, 8x8/thread
// Per-output accumulation = single ascending-k fma chain (matches BLAS refs).
// ---------------------------------------------------------------------------
__global__ __launch_bounds__(256) void sgemm128_nt(
    const float* __restrict__ A, const float* __restrict__ Bw,
    const float* __restrict__ bias, float* __restrict__ Cm,
    int M, int Nc, int K)
{
    __shared__ float As[8][128];
    __shared__ float Bs[8][128];
    int t = threadIdx.x;
    int m0 = blockIdx.y * 128;
    int n0 = blockIdx.x * 128;

    int aRow = t >> 1;          // 0..127
    int aK   = (t & 1) * 4;     // 0 or 4

    int ty = t >> 4, tx = t & 15;
    int rowBase = ty * 8, colBase = tx * 8;

    float acc[8][8];
#pragma unroll
    for (int i = 0; i < 8; i++)
#pragma unroll
        for (int j = 0; j < 8; j++) acc[i][j] = 0.f;

    const float* aPtr = A + (size_t)(m0 + aRow) * K + aK;
    const float* bPtr = Bw + (size_t)(n0 + aRow) * K + aK;
    bool aOk = (m0 + aRow) < M;
    bool bOk = (n0 + aRow) < Nc;

    for (int k0 = 0; k0 < K; k0 += 8) {
        float4 av = aOk ? *(const float4*)(aPtr + k0)
                        : make_float4(0.f, 0.f, 0.f, 0.f);
        float4 bv = bOk ? *(const float4*)(bPtr + k0)
                        : make_float4(0.f, 0.f, 0.f, 0.f);
        As[aK + 0][aRow] = av.x; As[aK + 1][aRow] = av.y;
        As[aK + 2][aRow] = av.z; As[aK + 3][aRow] = av.w;
        Bs[aK + 0][aRow] = bv.x; Bs[aK + 1][aRow] = bv.y;
        Bs[aK + 2][aRow] = bv.z; Bs[aK + 3][aRow] = bv.w;
        __syncthreads();

#pragma unroll
        for (int k = 0; k < 8; k++) {
            float a[8], b[8];
            *(float4*)(a)     = *(float4*)&As[k][rowBase];
            *(float4*)(a + 4) = *(float4*)&As[k][rowBase + 4];
            *(float4*)(b)     = *(float4*)&Bs[k][colBase];
            *(float4*)(b + 4) = *(float4*)&Bs[k][colBase + 4];
#pragma unroll
            for (int i = 0; i < 8; i++)
#pragma unroll
                for (int j = 0; j < 8; j++)
                    acc[i][j] += a[i] * b[j];
        }
        __syncthreads();
    }

    float bvals[8];
#pragma unroll
    for (int j = 0; j < 8; j++)
        bvals[j] = bias ? bias[n0 + colBase + j] : 0.f;

#pragma unroll
    for (int i = 0; i < 8; i++) {
        int m = m0 + rowBase + i;
        if (m >= M) continue;
        float* cp = Cm + (size_t)m * Nc + n0 + colBase;
        float4 c0, c1;
        c0.x = acc[i][0] + bvals[0]; c0.y = acc[i][1] + bvals[1];
        c0.z = acc[i][2] + bvals[2]; c0.w = acc[i][3] + bvals[3];
        c1.x = acc[i][4] + bvals[4]; c1.y = acc[i][5] + bvals[5];
        c1.z = acc[i][6] + bvals[6]; c1.w = acc[i][7] + bvals[7];
        *(float4*)(cp)     = c0;
        *(float4*)(cp + 4) = c1;
    }
}

// ---------------------------------------------------------------------------
// Attention scores: S[b,h,m,n] = scale * sum_d Q[m,d]*K[n,d]; 64x64 tiles
// Ascending-d fma chain; *0.125f (exact pow2) applied at store.
// ---------------------------------------------------------------------------
__global__ __launch_bounds__(256) void attn_scores()
{
    int z = blockIdx.z;
    int b = z / H_, h = z - b * H_;
    const float* __restrict__ Q  = g_qkv + (size_t)b * N_ * QKVC + h * HD_;
    const float* __restrict__ Kp = Q + C_;
    float* __restrict__ S = g_attn + (size_t)z * N_ * N_;

    int m0 = blockIdx.y * 64, n0 = blockIdx.x * 64;
    __shared__ float Qs[64 * 64]; // [k][m]
    __shared__ float Ks[64 * 64]; // [k][n]
    int t = threadIdx.x;

#pragma unroll
    for (int i = 0; i < 4; i++) {
        int f4  = t + i * 256;
        int row = f4 >> 4;
        int kq  = (f4 & 15) * 4;
        float4 qv = make_float4(0.f, 0.f, 0.f, 0.f);
        if (m0 + row < N_) qv = *(const float4*)(Q + (size_t)(m0 + row) * QKVC + kq);
        Qs[(kq + 0) * 64 + row] = qv.x; Qs[(kq + 1) * 64 + row] = qv.y;
        Qs[(kq + 2) * 64 + row] = qv.z; Qs[(kq + 3) * 64 + row] = qv.w;
        float4 kv = make_float4(0.f, 0.f, 0.f, 0.f);
        if (n0 + row < N_) kv = *(const float4*)(Kp + (size_t)(n0 + row) * QKVC + kq);
        Ks[(kq + 0) * 64 + row] = kv.x; Ks[(kq + 1) * 64 + row] = kv.y;
        Ks[(kq + 2) * 64 + row] = kv.z; Ks[(kq + 3) * 64 + row] = kv.w;
    }
    __syncthreads();

    int ty = t >> 4, tx = t & 15;
    float acc[4][4];
#pragma unroll
    for (int i = 0; i < 4; i++)
#pragma unroll
        for (int j = 0; j < 4; j++) acc[i][j] = 0.f;

#pragma unroll
    for (int k = 0; k < 64; k++) {
        float4 a  = *(float4*)&Qs[k * 64 + ty * 4];
        float4 bb = *(float4*)&Ks[k * 64 + tx * 4];
        float av[4] = {a.x, a.y, a.z, a.w};
        float bv[4] = {bb.x, bb.y, bb.z, bb.w};
#pragma unroll
        for (int i = 0; i < 4; i++)
#pragma unroll
            for (int j = 0; j < 4; j++)
                acc[i][j] += av[i] * bv[j];
    }

#pragma unroll
    for (int i = 0; i < 4; i++) {
        int m = m0 + ty * 4 + i;
        if (m >= N_) continue;
#pragma unroll
        for (int j = 0; j < 4; j++) {
            int n = n0 + tx * 4 + j;
            if (n < N_) S[m * N_ + n] = acc[i][j] * SCALE_;
        }
    }
}

// ---------------------------------------------------------------------------
// REF-MATCHED cls-row softmax, one block per (b,h).
// Reads pre-softmax scores from g_attn row 0 (runs BEFORE softmax_rows).
// max: order-free exact; exp: Cephes (== Eigen/XLA-CPU bit pattern);
// Z: strict ascending sequential sum; p = e / Z IEEE division.
// ---------------------------------------------------------------------------
__global__ __launch_bounds__(256) void cls_row_ref()
{
    int z = blockIdx.x;
    const float* __restrict__ S = g_attn + (size_t)z * N_ * N_; // row 0
    float* __restrict__ P = g_ph + (size_t)z * N_;

    int t = threadIdx.x;
    int lane = t & 31, wid = t >> 5;
    __shared__ float red[8];
    __shared__ float se[N_];
    __shared__ float zsh;

    float s[4];
    float mx = -INFINITY;
#pragma unroll
    for (int i = 0; i < 4; i++) {
        int j = t + i * 256;
        s[i] = (j < N_) ? S[j] : -INFINITY;
        mx = fmaxf(mx, s[i]);
    }
#pragma unroll
    for (int w = 16; w > 0; w >>= 1)
        mx = fmaxf(mx, __shfl_xor_sync(0xffffffffu, mx, w));
    if (lane == 0) red[wid] = mx;
    __syncthreads();
    mx = red[0];
#pragma unroll
    for (int w = 1; w < 8; w++) mx = fmaxf(mx, red[w]);

#pragma unroll
    for (int i = 0; i < 4; i++) {
        int j = t + i * 256;
        if (j < N_) se[j] = cephes_expf(s[i] - mx);
    }
    __syncthreads();

    if (t == 0) {
        float Z = 0.f;
        for (int j = 0; j < N_; j++) Z += se[j];   // canonical ascending order
        zsh = Z;
    }
    __syncthreads();
    float Z = zsh;

#pragma unroll
    for (int i = 0; i < 4; i++) {
        int j = t + i * 256;
        if (j < N_) P[j] = se[j] / Z;   // IEEE division
    }
}

// ---------------------------------------------------------------------------
// Row softmax over 785 elems (in place); fast path, feeds PV/out only.
// ---------------------------------------------------------------------------
__global__ __launch_bounds__(256) void softmax_rows()
{
    float* __restrict__ p = g_attn + (size_t)blockIdx.x * N_;
    int t = threadIdx.x;
    int lane = t & 31, wid = t >> 5;
    __shared__ float red[8];

    float v[4];
    float mx = -INFINITY;
#pragma unroll
    for (int i = 0; i < 4; i++) {
        int j = t + i * 256;
        v[i] = (j < N_) ? p[j] : -INFINITY;
        mx = fmaxf(mx, v[i]);
    }
#pragma unroll
    for (int s = 16; s > 0; s >>= 1)
        mx = fmaxf(mx, __shfl_xor_sync(0xffffffffu, mx, s));
    if (lane == 0) red[wid] = mx;
    __syncthreads();
    mx = red[0];
#pragma unroll
    for (int w = 1; w < 8; w++) mx = fmaxf(mx, red[w]);

    float sum = 0.f;
#pragma unroll
    for (int i = 0; i < 4; i++) {
        int j = t + i * 256;
        if (j < N_) { v[i] = __expf(v[i] - mx); sum += v[i]; }
    }
#pragma unroll
    for (int s = 16; s > 0; s >>= 1)
        sum += __shfl_xor_sync(0xffffffffu, sum, s);
    __syncthreads();
    if (lane == 0) red[wid] = sum;
    __syncthreads();
    sum = 0.f;
#pragma unroll
    for (int w = 0; w < 8; w++) sum += red[w];

    float inv = 1.f / sum;
#pragma unroll
    for (int i = 0; i < 4; i++) {
        int j = t + i * 256;
        if (j < N_) p[j] = v[i] * inv;
    }
}

// ---------------------------------------------------------------------------
// P @ V: O[b,h,m,d] = sum_k P[m,k] V[k,d];  64 m-rows x 64 d, BK=32
// ---------------------------------------------------------------------------
__global__ __launch_bounds__(256) void attn_pv()
{
    int z = blockIdx.z;
    int b = z / H_, h = z - b * H_;
    const float* __restrict__ P = g_attn + (size_t)z * N_ * N_;
    const float* __restrict__ V = g_qkv + (size_t)b * N_ * QKVC + 2 * C_ + h * HD_;
    float* __restrict__ O = g_attnout + (size_t)b * N_ * C_ + h * HD_;

    int m0 = blockIdx.y * 64;
    __shared__ float Ps[32 * 64]; // [k][m]
    __shared__ float Vs[32 * 64]; // [k][d]
    int t = threadIdx.x;
    int ty = t >> 4, tx = t & 15;

    float acc[4][4];
#pragma unroll
    for (int i = 0; i < 4; i++)
#pragma unroll
        for (int j = 0; j < 4; j++) acc[i][j] = 0.f;

    for (int k0 = 0; k0 < N_; k0 += 32) {
#pragma unroll
        for (int i = 0; i < 8; i++) {
            int e   = t + i * 256;
            int row = e >> 5;
            int kk  = e & 31;
            float pv = 0.f;
            if (m0 + row < N_ && k0 + kk < N_)
                pv = P[(m0 + row) * N_ + k0 + kk];
            Ps[kk * 64 + row] = pv;
        }
#pragma unroll
        for (int i = 0; i < 2; i++) {
            int f4 = t + i * 256;
            int kk = f4 >> 4;
            int d4 = (f4 & 15) * 4;
            float4 vv = make_float4(0.f, 0.f, 0.f, 0.f);
            if (k0 + kk < N_) vv = *(const float4*)(V + (size_t)(k0 + kk) * QKVC + d4);
            *(float4*)&Vs[kk * 64 + d4] = vv;
        }
        __syncthreads();

#pragma unroll
        for (int k = 0; k < 32; k++) {
            float4 a  = *(float4*)&Ps[k * 64 + ty * 4];
            float4 bb = *(float4*)&Vs[k * 64 + tx * 4];
            float av[4] = {a.x, a.y, a.z, a.w};
            float bv[4] = {bb.x, bb.y, bb.z, bb.w};
#pragma unroll
            for (int i = 0; i < 4; i++)
#pragma unroll
                for (int j = 0; j < 4; j++)
                    acc[i][j] += av[i] * bv[j];
        }
        __syncthreads();
    }

#pragma unroll
    for (int i = 0; i < 4; i++) {
        int m = m0 + ty * 4 + i;
        if (m >= N_) continue;
        float4 c;
        c.x = acc[i][0]; c.y = acc[i][1]; c.z = acc[i][2]; c.w = acc[i][3];
        *(float4*)(O + (size_t)m * C_ + tx * 4) = c;
    }
}

// ---------------------------------------------------------------------------
// cls_attn[b, j-1] = (sum_{h=0..11} p[b,h,j]) / 12.0f   (ascending h,
// IEEE division — matches jnp mean(axis=1))
// ---------------------------------------------------------------------------
__global__ void cls_mean(float* __restrict__ out_f)
{
    int b = blockIdx.x;
    for (int j = 1 + threadIdx.x; j < N_; j += blockDim.x) {
        float s = 0.f;
#pragma unroll
        for (int h = 0; h < H_; h++)
            s += g_ph[(size_t)(b * H_ + h) * N_ + j];
        float v = s / 12.0f;
        g_cls[b * NM1 + (j - 1)] = v;
        out_f[OFF_CLS + b * NM1 + (j - 1)] = v;
    }
}

// ---------------------------------------------------------------------------
// top-549 by rank counting (ties -> lower index, matches lax.top_k order)
// ---------------------------------------------------------------------------
__global__ void topk_sel(float* __restrict__ out_f)
{
    int b = blockIdx.x;
    __shared__ float sv[NM1];
    for (int j = threadIdx.x; j < NM1; j += blockDim.x)
        sv[j] = g_cls[b * NM1 + j];
    __syncthreads();
    for (int j = threadIdx.x; j < NM1; j += blockDim.x) {
        float v = sv[j];
        int rank = 0;
        for (int i = 0; i < NM1; i++) {
            float w = sv[i];
            rank += (w > v) || (w == v && i < j);
        }
        if (rank < LEFT) {
            g_idx[b * LEFT + rank] = j;
            out_f[OFF_IDX + b * LEFT + rank] = (float)j;
        }
    }
}

__global__ void bcast_index(float* __restrict__ out_f)
{
    int total = B_ * LEFT * C_;
    for (int i = blockIdx.x * blockDim.x + threadIdx.x; i < total;
         i += gridDim.x * blockDim.x) {
        int b = i / (LEFT * C_);
        int r = (i / C_) % LEFT;
        out_f[OFF_INDEX + i] = (float)g_idx[b * LEFT + r];
    }
}

// ---------------------------------------------------------------------------
extern "C" void kernel_launch(void* const* d_in, const int* in_sizes, int n_in,
                              void* d_out, int out_size)
{
    const float* x     = (const float*)d_in[0];
    const float* Wqkv  = (const float*)d_in[1];
    const float* Wproj = (const float*)d_in[2];
    const float* bproj = (const float*)d_in[3];
    float* out_f = (float*)d_out;

    float *p_qkv, *p_attnout;
    cudaGetSymbolAddress((void**)&p_qkv, g_qkv);
    cudaGetSymbolAddress((void**)&p_attnout, g_attnout);

    // 1. qkv = x @ Wqkv^T   (ascending-k fma chain per output)
    sgemm128_nt<<<dim3(QKVC / 128, (M_ + 127) / 128), 256>>>(
        x, Wqkv, nullptr, p_qkv, M_, QKVC, C_);

    // 2. S = scale * Q K^T  (ascending-d fma chain)
    attn_scores<<<dim3((N_ + 63) / 64, (N_ + 63) / 64, B_ * H_), 256>>>();

    // 3. ref-matched cls-row softmax: Cephes exp + sequential Z + IEEE div
    cls_row_ref<<<B_ * H_, 256>>>();

    // 4. softmax rows (fast, feeds PV)
    softmax_rows<<<B_ * H_ * N_, 256>>>();

    // 5. O = P V
    attn_pv<<<dim3(1, (N_ + 63) / 64, B_ * H_), 256>>>();

    // 6. out = O @ Wproj^T + bproj
    sgemm128_nt<<<dim3(C_ / 128, (M_ + 127) / 128), 256>>>(
        p_attnout, Wproj, bproj, out_f + OFF_OUT, M_, C_, C_);

    // 7. cls_attn mean over heads (ascending-h fp32, /12.0f)
    cls_mean<<<B_, 256>>>(out_f);

    // 8. top-k selection
    topk_sel<<<B_, 256>>>(out_f);

    // 9. broadcast index
    bcast_index<<<512, 256>>>(out_f);
}